// round 3
// baseline (speedup 1.0000x reference)
#include <cuda_runtime.h>
#include <math.h>

#define BATCH 2
#define SEQ 2048
#define DMODEL 1024
#define NHEADS 16
#define DKDIM 64
#define MROWS (BATCH*SEQ)      // 4096
#define NQKV (3*DMODEL)        // 3072

// Scratch (device globals -- no allocation in kernel_launch)
__device__ float g_q[(size_t)BATCH*NHEADS*SEQ*DKDIM];
__device__ float g_k[(size_t)BATCH*NHEADS*SEQ*DKDIM];
__device__ float g_v[(size_t)BATCH*NHEADS*SEQ*DKDIM];
__device__ float g_attn[(size_t)MROWS*DMODEL];

// ---------------------------------------------------------------------------
// Kernel 1: QKV GEMM (C = x * Wqkv^T) with fused RoPE epilogue, scattering
// q,k,v into [B,H,S,DK] scratch.
// Tile: 64x64, BK=16, 256 threads, 4x4 micro-tile per thread.
// ---------------------------------------------------------------------------
#define BM 64
#define BN 64
#define BK 16

__global__ __launch_bounds__(256)
void qkv_rope_kernel(const float* __restrict__ x,
                     const int*   __restrict__ tokpos,
                     const float* __restrict__ Wqkv)
{
    __shared__ float As[BK][BM + 4];   // stride 68 floats (16B aligned rows)
    __shared__ float Bs[BK][BN + 4];

    const int tid  = threadIdx.x;
    const int row0 = blockIdx.x * BM;
    const int col0 = blockIdx.y * BN;
    const int tx = tid & 15;
    const int ty = tid >> 4;

    const int lr = tid >> 2;          // 0..63
    const int lk = (tid & 3) * 4;     // 0,4,8,12

    float c[4][4] = {};

    for (int k0 = 0; k0 < DMODEL; k0 += BK) {
        float4 a4 = *(const float4*)(x    + (size_t)(row0 + lr) * DMODEL + k0 + lk);
        float4 b4 = *(const float4*)(Wqkv + (size_t)(col0 + lr) * DMODEL + k0 + lk);
        __syncthreads();
        As[lk+0][lr] = a4.x; As[lk+1][lr] = a4.y; As[lk+2][lr] = a4.z; As[lk+3][lr] = a4.w;
        Bs[lk+0][lr] = b4.x; Bs[lk+1][lr] = b4.y; Bs[lk+2][lr] = b4.z; Bs[lk+3][lr] = b4.w;
        __syncthreads();
        #pragma unroll
        for (int kk = 0; kk < BK; kk++) {
            float4 av = *(const float4*)&As[kk][ty*4];
            float4 bv = *(const float4*)&Bs[kk][tx*4];
            float a[4] = {av.x, av.y, av.z, av.w};
            float b[4] = {bv.x, bv.y, bv.z, bv.w};
            #pragma unroll
            for (int i = 0; i < 4; i++)
                #pragma unroll
                for (int j = 0; j < 4; j++)
                    c[i][j] += a[i] * b[j];
        }
    }

    // Epilogue: RoPE for q,k; plain scatter for v. Each thread owns 4
    // consecutive cols aligned to 4 => even/odd pairs are intra-thread.
    #pragma unroll
    for (int i = 0; i < 4; i++) {
        const int m = row0 + ty*4 + i;
        const int b = m / SEQ;
        const int s = m % SEQ;
        const float pos = (float)tokpos[s];
        #pragma unroll
        for (int jj = 0; jj < 4; jj += 2) {
            const int o      = col0 + tx*4 + jj;
            const int which  = o >> 10;          // 0=q 1=k 2=v
            const int within = o & 1023;
            const int h      = within >> 6;
            const int d      = within & 63;      // even
            const float e0 = c[i][jj];
            const float e1 = c[i][jj+1];
            float* dst;
            if (which == 2) {
                dst = g_v + ((size_t)(b*NHEADS + h)*SEQ + s)*DKDIM + d;
                dst[0] = e0; dst[1] = e1;
            } else {
                const float freq = powf(10000.0f, -(float)d * (1.0f/64.0f));
                const float ang  = pos * freq;
                float sn, cs;
                sincosf(ang, &sn, &cs);
                dst = (which ? g_k : g_q) + ((size_t)(b*NHEADS + h)*SEQ + s)*DKDIM + d;
                dst[0] = e0*cs - e1*sn;
                dst[1] = e0*sn + e1*cs;
            }
        }
    }
}

// ---------------------------------------------------------------------------
// Kernel 2: causal flash attention, fp32.
// Block = 64 threads, each owns one query row (q & acc in registers).
// Key tiles of 32 rows; K/V tiles + padded score buffer in SMEM (~24.5 KB).
// ---------------------------------------------------------------------------
#define FBM 64
#define FBN 32

__global__ __launch_bounds__(64)
void attn_kernel()
{
    __shared__ float Ksh[FBN][DKDIM];       // 8 KB
    __shared__ float Vsh[FBN][DKDIM];       // 8 KB
    __shared__ float Ssh[FBM][FBN + 1];     // 8.25 KB, conflict-free

    const int tid = threadIdx.x;
    const int qb  = blockIdx.x;             // 0..31
    const int bh  = blockIdx.y;             // 0..31
    const int qi  = qb*FBM + tid;           // query row (== s)

    const float* qptr = g_q + ((size_t)bh*SEQ + qi)*DKDIM;
    float4 qr[16];
    #pragma unroll
    for (int i = 0; i < 16; i++) {
        qr[i] = *(const float4*)(qptr + i*4);
        qr[i].x *= 0.125f; qr[i].y *= 0.125f; qr[i].z *= 0.125f; qr[i].w *= 0.125f;
    }

    float4 acc[16];
    #pragma unroll
    for (int i = 0; i < 16; i++) acc[i] = make_float4(0.f, 0.f, 0.f, 0.f);
    float mrow = -1e30f, lrow = 0.f;

    const int nkt = 2*qb + 2;               // key tiles (causal)
    const float* kbaseptr = g_k + (size_t)bh*SEQ*DKDIM;
    const float* vbaseptr = g_v + (size_t)bh*SEQ*DKDIM;

    for (int kt = 0; kt < nkt; kt++) {
        const int kbase = kt * FBN;
        __syncthreads();
        const float4* kp = (const float4*)(kbaseptr + (size_t)kbase*DKDIM);
        const float4* vp = (const float4*)(vbaseptr + (size_t)kbase*DKDIM);
        #pragma unroll
        for (int i = 0; i < 8; i++) {       // 32*64 floats = 512 float4s / 64 thr
            int idx = tid + i*64;
            ((float4*)Ksh)[idx] = kp[idx];
            ((float4*)Vsh)[idx] = vp[idx];
        }
        __syncthreads();

        float tmax = -1e30f;
        #pragma unroll 4
        for (int j = 0; j < FBN; j++) {
            float sc = 0.f;
            #pragma unroll
            for (int dc = 0; dc < 16; dc++) {
                float4 k4 = *(const float4*)&Ksh[j][dc*4];
                sc += qr[dc].x*k4.x + qr[dc].y*k4.y + qr[dc].z*k4.z + qr[dc].w*k4.w;
            }
            if (kbase + j > qi) sc = -1e30f;  // causal mask
            Ssh[tid][j] = sc;
            tmax = fmaxf(tmax, sc);
        }

        const float newm = fmaxf(mrow, tmax);
        const float corr = __expf(mrow - newm);
        mrow = newm;
        lrow *= corr;
        #pragma unroll
        for (int i = 0; i < 16; i++) {
            acc[i].x *= corr; acc[i].y *= corr; acc[i].z *= corr; acc[i].w *= corr;
        }

        #pragma unroll 4
        for (int j = 0; j < FBN; j++) {
            const float p = __expf(Ssh[tid][j] - newm);
            lrow += p;
            #pragma unroll
            for (int dc = 0; dc < 16; dc++) {
                float4 v4 = *(const float4*)&Vsh[j][dc*4];
                acc[dc].x += p*v4.x; acc[dc].y += p*v4.y;
                acc[dc].z += p*v4.z; acc[dc].w += p*v4.w;
            }
        }
    }

    const float inv = 1.0f / lrow;
    const int b = bh / NHEADS, h = bh % NHEADS;
    float* dst = g_attn + ((size_t)(b*SEQ + qi))*DMODEL + h*DKDIM;
    #pragma unroll
    for (int dc = 0; dc < 16; dc++) {
        float4 o4 = make_float4(acc[dc].x*inv, acc[dc].y*inv, acc[dc].z*inv, acc[dc].w*inv);
        *(float4*)(dst + dc*4) = o4;
    }
}

// ---------------------------------------------------------------------------
// Kernel 3: output GEMM (out = attn * Wout^T), same tiling as kernel 1.
// ---------------------------------------------------------------------------
__global__ __launch_bounds__(256)
void out_gemm_kernel(const float* __restrict__ Wout, float* __restrict__ out)
{
    __shared__ float As[BK][BM + 4];
    __shared__ float Bs[BK][BN + 4];

    const int tid  = threadIdx.x;
    const int row0 = blockIdx.x * BM;
    const int col0 = blockIdx.y * BN;
    const int tx = tid & 15;
    const int ty = tid >> 4;
    const int lr = tid >> 2;
    const int lk = (tid & 3) * 4;

    float c[4][4] = {};

    for (int k0 = 0; k0 < DMODEL; k0 += BK) {
        float4 a4 = *(const float4*)(g_attn + (size_t)(row0 + lr) * DMODEL + k0 + lk);
        float4 b4 = *(const float4*)(Wout   + (size_t)(col0 + lr) * DMODEL + k0 + lk);
        __syncthreads();
        As[lk+0][lr] = a4.x; As[lk+1][lr] = a4.y; As[lk+2][lr] = a4.z; As[lk+3][lr] = a4.w;
        Bs[lk+0][lr] = b4.x; Bs[lk+1][lr] = b4.y; Bs[lk+2][lr] = b4.z; Bs[lk+3][lr] = b4.w;
        __syncthreads();
        #pragma unroll
        for (int kk = 0; kk < BK; kk++) {
            float4 av = *(const float4*)&As[kk][ty*4];
            float4 bv = *(const float4*)&Bs[kk][tx*4];
            float a[4] = {av.x, av.y, av.z, av.w};
            float b[4] = {bv.x, bv.y, bv.z, bv.w};
            #pragma unroll
            for (int i = 0; i < 4; i++)
                #pragma unroll
                for (int j = 0; j < 4; j++)
                    c[i][j] += a[i] * b[j];
        }
    }

    #pragma unroll
    for (int i = 0; i < 4; i++) {
        const int m = row0 + ty*4 + i;
        float4 o4 = make_float4(c[i][0], c[i][1], c[i][2], c[i][3]);
        *(float4*)(out + (size_t)m*DMODEL + col0 + tx*4) = o4;
    }
}

// ---------------------------------------------------------------------------
extern "C" void kernel_launch(void* const* d_in, const int* in_sizes, int n_in,
                              void* d_out, int out_size)
{
    const float* x      = (const float*)d_in[0];
    const int*   tokpos = (const int*)  d_in[1];
    const float* Wqkv   = (const float*)d_in[2];
    const float* Wout   = (const float*)d_in[3];
    float*       out    = (float*)d_out;

    qkv_rope_kernel<<<dim3(MROWS/BM, NQKV/BN), 256>>>(x, tokpos, Wqkv);
    attn_kernel<<<dim3(SEQ/FBM, BATCH*NHEADS), 64>>>();
    out_gemm_kernel<<<dim3(MROWS/BM, DMODEL/BN), 256>>>(Wout, out);
}